// round 15
// baseline (speedup 1.0000x reference)
#include <cuda_runtime.h>
#include <cuda_bf16.h>
#include <cstdint>

#define SEQL 601
#define BATCH 512
#define ZS 100
#define FLATD 5
#define HID 256
#define IN1 105   // ZS + FLATD
#define TPB 544   // 512 consumer threads + 1 producer warp
#define CLU 8
#define NSLOT 3
#define NCHUNK 34         // per step: 2 fc1 + 16 W1 + 16 W2
#define CHUNK_B 65536
#define CHUNK_U 16384     // 32-bit words per chunk

// ---------------- smem layout (dynamic, bytes) --------------------------------
#define RING_OFF 0
#define MB_OFF   196608   // 3 x (full,empty) pairs, 16B each
#define A1_OFF   196672
#define A2_OFF   204864
#define RED_OFF  213056
#define INSM_OFF 229440
#define SMEM_TOT 231488

// ---------------- scratch (__device__ globals; no allocation) -----------------
// Streamed image per step (rebuilt each launch by repack):
//  words [0,32768)        : fc1t as float [k(128, zero-pad>=105)][u]
//  words [32768,294912)   : W1 [k][u] uint = (bf16 ih | bf16 hh<<16) x4 gates
//  words [294912,557056)  : W2 same
__device__ unsigned g_stream[NCHUNK * CHUNK_U];
__device__ float g_b1[HID * 4];   // [u][gate] = b_ih + b_hh
__device__ float g_b2[HID * 4];

// ---------------- weight repack kernel ----------------------------------------
__global__ void repack_kernel(const float* __restrict__ w_ih1,
                              const float* __restrict__ w_hh1,
                              const float* __restrict__ w_ih2,
                              const float* __restrict__ w_hh2,
                              const float* __restrict__ b_ih1,
                              const float* __restrict__ b_hh1,
                              const float* __restrict__ b_ih2,
                              const float* __restrict__ b_hh2,
                              const float* __restrict__ fc1_w) {
    int idx = blockIdx.x * blockDim.x + threadIdx.x;
    const int FCN = 32768;
    const int NP = HID * HID * 4;  // 262144 words per LSTM
    if (idx < FCN) {
        int k = idx >> 8, u = idx & 255;
        ((float*)g_stream)[idx] = (k < IN1) ? fc1_w[u * IN1 + k] : 0.0f;
    } else if (idx < FCN + 2 * NP) {
        int e = idx - FCN;
        int m = e / NP;
        int r = e % NP;
        int g = r & 3;
        int u = (r >> 2) & (HID - 1);
        int k = r >> 10;
        const float* wih = m ? w_ih2 : w_ih1;
        const float* whh = m ? w_hh2 : w_hh1;
        unsigned a = (unsigned)__bfloat16_as_ushort(__float2bfloat16(wih[(g * HID + u) * HID + k]));
        unsigned b = (unsigned)__bfloat16_as_ushort(__float2bfloat16(whh[(g * HID + u) * HID + k]));
        g_stream[idx] = a | (b << 16);
    } else if (idx < FCN + 2 * NP + 2 * HID * 4) {
        int e = idx - FCN - 2 * NP;
        int which = e / (HID * 4);
        int r = e % (HID * 4);
        int g = r & 3, u = r >> 2;
        if (which == 0)
            g_b1[r] = b_ih1[g * HID + u] + b_hh1[g * HID + u];
        else
            g_b2[r] = b_ih2[g * HID + u] + b_hh2[g * HID + u];
    }
}

// ---------------- activations -------------------------------------------------
__device__ __forceinline__ float sigm_f(float x) {
    return __fdividef(1.0f, 1.0f + __expf(-x));
}
__device__ __forceinline__ float tanh_f(float x) {
    float e = __expf(-2.0f * x);
    return __fdividef(2.0f, 1.0f + e) - 1.0f;
}

// ---------------- f32x2 helpers -----------------------------------------------
__device__ __forceinline__ unsigned long long cvtw(unsigned c) {
    unsigned lo = c << 16;
    unsigned hi = c & 0xffff0000u;
    unsigned long long p;
    asm("mov.b64 %0, {%1, %2};" : "=l"(p) : "r"(lo), "r"(hi));
    return p;
}
__device__ __forceinline__ void fma2(unsigned long long& acc, unsigned long long w,
                                     unsigned long long xh) {
    asm("fma.rn.f32x2 %0, %1, %2, %3;" : "=l"(acc) : "l"(w), "l"(xh), "l"(acc));
}
__device__ __forceinline__ float redu0(unsigned long long a) {
    unsigned lo, hi;
    asm("mov.b64 {%0, %1}, %2;" : "=r"(lo), "=r"(hi) : "l"(a));
    return __uint_as_float(lo) + __uint_as_float(hi);
}

// ---------------- mbarrier / cluster helpers -----------------------------------
__device__ __forceinline__ uint32_t ctarank() {
    uint32_t r;
    asm("mov.u32 %0, %%cluster_ctarank;" : "=r"(r));
    return r;
}
__device__ __forceinline__ void mbar_init(uint32_t a, uint32_t cnt) {
    asm volatile("mbarrier.init.shared.b64 [%0], %1;" :: "r"(a), "r"(cnt) : "memory");
}
__device__ __forceinline__ void mbar_expect(uint32_t a, uint32_t bytes) {
    asm volatile("mbarrier.arrive.expect_tx.shared.b64 _, [%0], %1;"
                 :: "r"(a), "r"(bytes) : "memory");
}
__device__ __forceinline__ void mbar_arrive_rank0(uint32_t a) {
    asm volatile(
        "{\n\t.reg .b32 ra;\n\t"
        "mapa.shared::cluster.u32 ra, %0, 0;\n\t"
        "mbarrier.arrive.shared::cluster.b64 _, [ra];\n\t}"
        :: "r"(a) : "memory");
}
__device__ __forceinline__ void mbar_wait_acq(uint32_t a, uint32_t ph) {
    asm volatile(
        "{\n\t.reg .pred P;\n\t"
        "WL_%=:\n\t"
        "mbarrier.try_wait.parity.acquire.cta.shared::cta.b64 P, [%0], %1, 0x989680;\n\t"
        "@P bra.uni WD_%=;\n\t"
        "bra.uni WL_%=;\n\t"
        "WD_%=:\n\t}"
        :: "r"(a), "r"(ph) : "memory");
}
__device__ __forceinline__ void mbar_wait_rlx(uint32_t a, uint32_t ph) {
    asm volatile(
        "{\n\t.reg .pred P;\n\t"
        "WL_%=:\n\t"
        "mbarrier.try_wait.parity.relaxed.cta.shared::cta.b64 P, [%0], %1, 0x989680;\n\t"
        "@P bra.uni WD_%=;\n\t"
        "bra.uni WL_%=;\n\t"
        "WD_%=:\n\t}"
        :: "r"(a), "r"(ph) : "memory");
}
#define CONS_BAR() asm volatile("bar.sync 1, 512;" ::: "memory")
#define CLUSTER_ARV() asm volatile("barrier.cluster.arrive.aligned;" ::: "memory")
#define CLUSTER_WT()  asm volatile("barrier.cluster.wait.aligned;" ::: "memory")

// ---------------- one k2 (2 k's) of LSTM math -----------------------------------
__device__ __forceinline__ void k2_block(uint4 wA, uint4 wB,
                                         ulonglong2 xv0, ulonglong2 xv1,
                                         ulonglong2 xv2, ulonglong2 xv3,
                                         unsigned long long* acc) {
    unsigned long long wi = cvtw(wA.x), wf = cvtw(wA.y), wg = cvtw(wA.z), wo = cvtw(wA.w);
    fma2(acc[0], wi, xv0.x); fma2(acc[4], wf, xv0.x); fma2(acc[8],  wg, xv0.x); fma2(acc[12], wo, xv0.x);
    fma2(acc[1], wi, xv1.x); fma2(acc[5], wf, xv1.x); fma2(acc[9],  wg, xv1.x); fma2(acc[13], wo, xv1.x);
    fma2(acc[2], wi, xv2.x); fma2(acc[6], wf, xv2.x); fma2(acc[10], wg, xv2.x); fma2(acc[14], wo, xv2.x);
    fma2(acc[3], wi, xv3.x); fma2(acc[7], wf, xv3.x); fma2(acc[11], wg, xv3.x); fma2(acc[15], wo, xv3.x);
    wi = cvtw(wB.x); wf = cvtw(wB.y); wg = cvtw(wB.z); wo = cvtw(wB.w);
    fma2(acc[0], wi, xv0.y); fma2(acc[4], wf, xv0.y); fma2(acc[8],  wg, xv0.y); fma2(acc[12], wo, xv0.y);
    fma2(acc[1], wi, xv1.y); fma2(acc[5], wf, xv1.y); fma2(acc[9],  wg, xv1.y); fma2(acc[13], wo, xv1.y);
    fma2(acc[2], wi, xv2.y); fma2(acc[6], wf, xv2.y); fma2(acc[10], wg, xv2.y); fma2(acc[14], wo, xv2.y);
    fma2(acc[3], wi, xv3.y); fma2(acc[7], wf, xv3.y); fma2(acc[11], wg, xv3.y); fma2(acc[15], wo, xv3.y);
}

// ---------------- main persistent kernel ---------------------------------------
// 128 CTAs in 16 clusters of 8. CTA owns 4 batch rows. Rank 0 of each cluster
// multicasts the 2.2MB/step weight image through a 3x64KB smem ring to all 8.
__global__ void __launch_bounds__(TPB, 1) __cluster_dims__(CLU, 1, 1)
gen_kernel(const float* __restrict__ z,         // [B][S][ZS]
           const float* __restrict__ prev_gen,  // [B][FLATD]
           const float* __restrict__ fc1_b,     // [HID]
           const float* __restrict__ fc2_w,     // [FLATD][HID]
           const float* __restrict__ fc2_b,     // [FLATD]
           float* __restrict__ out)             // [B][S][FLATD]
{
    extern __shared__ __align__(16) char sm[];
    char* ring = sm + RING_OFF;
    const uint32_t ring_sa = (uint32_t)__cvta_generic_to_shared(ring);
    const uint32_t mb = (uint32_t)__cvta_generic_to_shared(sm + MB_OFF);
    float2 (*A1)[HID] = (float2(*)[HID])(sm + A1_OFF);   // (x_t, h1_{t-1})
    float2 (*A2)[HID] = (float2(*)[HID])(sm + A2_OFF);   // (h1_t, h2_{t-1})
    float (*red)[HID] = (float(*)[HID])(sm + RED_OFF);   // cross-half partials
    float (*insm)[128] = (float(*)[128])(sm + INSM_OFF); // [row][k]; 100..104=prev, >=105 zero

    const int tid = threadIdx.x;
    const uint32_t rank = ctarank();
    const int b0 = blockIdx.x * 4;

    // ---- init ----
    if (tid == 0) {
#pragma unroll
        for (int s = 0; s < NSLOT; s++) {
            mbar_init(mb + 16 * s, 1);        // full[s]
            mbar_init(mb + 16 * s + 8, CLU);  // empty[s]
        }
#pragma unroll
        for (int s = 0; s < NSLOT; s++) mbar_expect(mb + 16 * s, CHUNK_B);  // arm first uses
    }
    if (tid < 512) {
        const int u = tid & (HID - 1);
        if (tid < 256) {
#pragma unroll
            for (int r = 0; r < 4; r++) {
                A1[r][u].y = 0.0f;
                A2[r][u].y = 0.0f;
            }
        }
        if (tid < 20) {
            int r = tid / 5, j = tid % 5;
            insm[r][ZS + j] = prev_gen[(b0 + r) * FLATD + j];
        }
        if (tid < 92) {  // zero pad cols 105..127
            int r = tid / 23, k = IN1 + tid % 23;
            insm[r][k] = 0.0f;
        }
    }
    __syncthreads();   // all 544: init visible
    CLUSTER_ARV();
    CLUSTER_WT();      // all CTAs armed before any multicast

    if (tid < 512) {
        // ================= CONSUMER =================
        const int u = tid & (HID - 1);
        const int half = tid >> 8;
        float c1[2] = {0.f, 0.f};
        float c2[2] = {0.f, 0.f};
        const float fb = fc1_b[u];
        const float4 b1v = ((const float4*)g_b1)[u];
        const float4 b2v = ((const float4*)g_b2)[u];
        int cs = 0, cuse = 0;  // ring cursor

        for (int t = 0; t < SEQL; ++t) {
            // ---- stage 1: z rows into insm ----
            if (tid < 4 * ZS) {
                int r = tid / ZS, k = tid % ZS;
                insm[r][k] = z[(size_t)(b0 + r) * (SEQL * ZS) + (size_t)t * ZS + k];
            }
            CONS_BAR();  // insm ready

            // ---- stage 2: fc1 (2 chunks) -> A1.x; half0 rows 0,1 / half1 rows 2,3 ----
            {
                int r0 = half * 2, r1 = r0 + 1;
                float a0 = fb, a1 = fb;
#pragma unroll 1
                for (int j = 0; j < 2; j++) {
                    mbar_wait_acq(mb + 16 * cs, cuse & 1);
                    const float* wf = (const float*)(ring + cs * CHUNK_B);
#pragma unroll 8
                    for (int k = 0; k < 64; k++) {
                        float w = wf[k * HID + u];
                        a0 += w * insm[r0][64 * j + k];
                        a1 += w * insm[r1][64 * j + k];
                    }
                    CONS_BAR();
                    if (tid == 0) {
                        mbar_expect(mb + 16 * cs, CHUNK_B);
                        mbar_arrive_rank0(mb + 16 * cs + 8);
                    }
                    if (++cs == NSLOT) { cs = 0; cuse++; }
                }
                A1[r0][u].x = fmaxf(a0, 0.0f);
                A1[r1][u].x = fmaxf(a1, 0.0f);
            }
            CONS_BAR();  // A1 = (x, h1prev) ready

            // ---- stages 3&4: LSTM1 then LSTM2, 16 chunks each ----
#pragma unroll 1
            for (int stage = 0; stage < 2; stage++) {
                unsigned long long acc[16];
#pragma unroll
                for (int j = 0; j < 16; j++) acc[j] = 0ull;
                const float2(*Ax)[HID] = stage ? A2 : A1;
                const ulonglong2* x0 = (const ulonglong2*)Ax[0];
                const ulonglong2* x1 = (const ulonglong2*)Ax[1];
                const ulonglong2* x2 = (const ulonglong2*)Ax[2];
                const ulonglong2* x3 = (const ulonglong2*)Ax[3];
#pragma unroll 1
                for (int jc = 0; jc < 16; jc++) {
                    mbar_wait_acq(mb + 16 * cs, cuse & 1);
                    const uint4* wp = (const uint4*)(ring + cs * CHUNK_B) + (8 * half) * HID + u;
                    int xb = 8 * jc + 4 * half;
#pragma unroll
                    for (int kk = 0; kk < 4; kk++) {
                        uint4 wA = wp[(2 * kk) * HID];
                        uint4 wB = wp[(2 * kk + 1) * HID];
                        k2_block(wA, wB, x0[xb + kk], x1[xb + kk], x2[xb + kk], x3[xb + kk], acc);
                    }
                    CONS_BAR();
                    if (tid == 0) {
                        mbar_expect(mb + 16 * cs, CHUNK_B);
                        mbar_arrive_rank0(mb + 16 * cs + 8);
                    }
                    if (++cs == NSLOT) { cs = 0; cuse++; }
                }
                // merge halves + activations (other half's rows via red)
                int ro = 2 * (1 - half);
#pragma unroll
                for (int g = 0; g < 4; g++) {
                    red[g * 4 + ro][u] = redu0(acc[g * 4 + ro]);
                    red[g * 4 + ro + 1][u] = redu0(acc[g * 4 + ro + 1]);
                }
                CONS_BAR();  // partials ready; all Ax reads done
                const float4 bv = stage ? b2v : b1v;
                float* cc = stage ? c2 : c1;
                int rs = 2 * half;
#pragma unroll
                for (int rr = 0; rr < 2; rr++) {
                    int r = rs + rr;
                    float iv = sigm_f(redu0(acc[0 + r]) + red[0 + r][u] + bv.x);
                    float fv = sigm_f(redu0(acc[4 + r]) + red[4 + r][u] + bv.y);
                    float gv = tanh_f(redu0(acc[8 + r]) + red[8 + r][u] + bv.z);
                    float ov = sigm_f(redu0(acc[12 + r]) + red[12 + r][u] + bv.w);
                    float cn = fv * cc[rr] + iv * gv;
                    cc[rr] = cn;
                    float hv = ov * tanh_f(cn);
                    if (stage == 0) {
                        A1[r][u].y = hv;  // h1 for t+1
                        A2[r][u].x = hv;  // input to LSTM2 now
                    } else {
                        A2[r][u].y = hv;  // h2 for t+1 / fc2
                    }
                }
                CONS_BAR();
            }

            // ---- stage 5: fc2 + tanh -> prev + output ----
            {
                int wid = tid >> 5, lane = tid & 31;
                for (int p = wid; p < 20; p += 16) {
                    int j = p >> 2, r = p & 3;
                    float s = 0.0f;
#pragma unroll
                    for (int i = 0; i < 8; i++) {
                        int uu = lane + 32 * i;
                        s += fc2_w[j * HID + uu] * A2[r][uu].y;
                    }
#pragma unroll
                    for (int o = 16; o; o >>= 1) s += __shfl_down_sync(0xffffffffu, s, o);
                    if (lane == 0) {
                        float v = tanh_f(s + fc2_b[j]);
                        insm[r][ZS + j] = v;
                        out[(size_t)(b0 + r) * (SEQL * FLATD) + (size_t)t * FLATD + j] = v;
                    }
                }
            }
            // next iteration's first CONS_BAR orders stage5 writes before fc1 reads
        }
    } else if (tid == 512 && rank == 0) {
        // ================= PRODUCER (one lane) =================
        int s = 0, use = 0;
        for (int c = 0; c < SEQL * NCHUNK; ++c) {
            if (c >= NSLOT) mbar_wait_rlx(mb + 16 * s + 8, (use + 1) & 1);  // (use-1)&1
            const char* src = (const char*)g_stream + (size_t)(c % NCHUNK) * CHUNK_B;
            asm volatile(
                "cp.async.bulk.shared::cluster.global.mbarrier::complete_tx::bytes"
                ".multicast::cluster [%0], [%1], %2, [%3], %4;"
                :: "r"(ring_sa + s * CHUNK_B), "l"(src), "r"(CHUNK_B),
                   "r"(mb + 16 * s), "h"((unsigned short)0xFF)
                : "memory");
            if (++s == NSLOT) { s = 0; use++; }
        }
    }

    CLUSTER_ARV();
    CLUSTER_WT();  // no CTA exits while multicasts may target it
}

// ---------------- launch --------------------------------------------------------
extern "C" void kernel_launch(void* const* d_in, const int* in_sizes, int n_in,
                              void* d_out, int out_size) {
    (void)in_sizes; (void)n_in; (void)out_size;
    const float* z        = (const float*)d_in[0];
    const float* prev_gen = (const float*)d_in[1];
    const float* fc1_w    = (const float*)d_in[2];
    const float* fc1_b    = (const float*)d_in[3];
    const float* w_ih1    = (const float*)d_in[4];
    const float* w_hh1    = (const float*)d_in[5];
    const float* b_ih1    = (const float*)d_in[6];
    const float* b_hh1    = (const float*)d_in[7];
    const float* w_ih2    = (const float*)d_in[8];
    const float* w_hh2    = (const float*)d_in[9];
    const float* b_ih2    = (const float*)d_in[10];
    const float* b_hh2    = (const float*)d_in[11];
    const float* fc2_w    = (const float*)d_in[12];
    const float* fc2_b    = (const float*)d_in[13];
    float* out = (float*)d_out;

    const int total = NCHUNK * CHUNK_U + 2 * HID * 4;
    repack_kernel<<<(total + 255) / 256, 256>>>(w_ih1, w_hh1, w_ih2, w_hh2,
                                                b_ih1, b_hh1, b_ih2, b_hh2, fc1_w);

    cudaFuncSetAttribute(gen_kernel, cudaFuncAttributeMaxDynamicSharedMemorySize,
                         SMEM_TOT);
    gen_kernel<<<BATCH / 4, TPB, SMEM_TOT>>>(z, prev_gen, fc1_b, fc2_w, fc2_b, out);
}

// round 16
// speedup vs baseline: 1.0621x; 1.0621x over previous
#include <cuda_runtime.h>
#include <cuda_bf16.h>
#include <cstdint>

#define SEQL 601
#define BATCH 512
#define ZS 100
#define FLATD 5
#define HID 256
#define IN1 105   // ZS + FLATD
#define TPB 544   // 512 consumer threads + 1 producer warp
#define CLU 8
#define NSLOT 3
#define NCHUNK 34         // per step: 2 fc1 + 16 W1 + 16 W2
#define CHUNK_B 65536
#define CHUNK_U 16384     // 32-bit words per chunk
#define NWARPC 16         // consumer warps per CTA

// ---------------- smem layout (dynamic, bytes) --------------------------------
#define RING_OFF 0
#define MB_OFF   196608   // 3 x (full,empty) pairs, 16B each
#define A1_OFF   196672
#define A2_OFF   204864
#define RED_OFF  213056
#define INSM_OFF 229440
#define SMEM_TOT 231488

// ---------------- scratch (__device__ globals; no allocation) -----------------
// Streamed image per step (rebuilt each launch by repack):
//  words [0,32768)        : fc1t as float [k(128, zero-pad>=105)][u]
//  words [32768,294912)   : W1 [k][u] uint = (bf16 ih | bf16 hh<<16) x4 gates
//  words [294912,557056)  : W2 same
__device__ unsigned g_stream[NCHUNK * CHUNK_U];
__device__ float g_b1[HID * 4];   // [u][gate] = b_ih + b_hh
__device__ float g_b2[HID * 4];

// ---------------- weight repack kernel ----------------------------------------
__global__ void repack_kernel(const float* __restrict__ w_ih1,
                              const float* __restrict__ w_hh1,
                              const float* __restrict__ w_ih2,
                              const float* __restrict__ w_hh2,
                              const float* __restrict__ b_ih1,
                              const float* __restrict__ b_hh1,
                              const float* __restrict__ b_ih2,
                              const float* __restrict__ b_hh2,
                              const float* __restrict__ fc1_w) {
    int idx = blockIdx.x * blockDim.x + threadIdx.x;
    const int FCN = 32768;
    const int NP = HID * HID * 4;  // 262144 words per LSTM
    if (idx < FCN) {
        int k = idx >> 8, u = idx & 255;
        ((float*)g_stream)[idx] = (k < IN1) ? fc1_w[u * IN1 + k] : 0.0f;
    } else if (idx < FCN + 2 * NP) {
        int e = idx - FCN;
        int m = e / NP;
        int r = e % NP;
        int g = r & 3;
        int u = (r >> 2) & (HID - 1);
        int k = r >> 10;
        const float* wih = m ? w_ih2 : w_ih1;
        const float* whh = m ? w_hh2 : w_hh1;
        unsigned a = (unsigned)__bfloat16_as_ushort(__float2bfloat16(wih[(g * HID + u) * HID + k]));
        unsigned b = (unsigned)__bfloat16_as_ushort(__float2bfloat16(whh[(g * HID + u) * HID + k]));
        g_stream[idx] = a | (b << 16);
    } else if (idx < FCN + 2 * NP + 2 * HID * 4) {
        int e = idx - FCN - 2 * NP;
        int which = e / (HID * 4);
        int r = e % (HID * 4);
        int g = r & 3, u = r >> 2;
        if (which == 0)
            g_b1[r] = b_ih1[g * HID + u] + b_hh1[g * HID + u];
        else
            g_b2[r] = b_ih2[g * HID + u] + b_hh2[g * HID + u];
    }
}

// ---------------- activations -------------------------------------------------
__device__ __forceinline__ float sigm_f(float x) {
    return __fdividef(1.0f, 1.0f + __expf(-x));
}
__device__ __forceinline__ float tanh_f(float x) {
    float e = __expf(-2.0f * x);
    return __fdividef(2.0f, 1.0f + e) - 1.0f;
}

// ---------------- f32x2 helpers -----------------------------------------------
__device__ __forceinline__ unsigned long long cvtw(unsigned c) {
    unsigned lo = c << 16;
    unsigned hi = c & 0xffff0000u;
    unsigned long long p;
    asm("mov.b64 %0, {%1, %2};" : "=l"(p) : "r"(lo), "r"(hi));
    return p;
}
__device__ __forceinline__ void fma2(unsigned long long& acc, unsigned long long w,
                                     unsigned long long xh) {
    asm("fma.rn.f32x2 %0, %1, %2, %3;" : "=l"(acc) : "l"(w), "l"(xh), "l"(acc));
}
__device__ __forceinline__ float redu0(unsigned long long a) {
    unsigned lo, hi;
    asm("mov.b64 {%0, %1}, %2;" : "=r"(lo), "=r"(hi) : "l"(a));
    return __uint_as_float(lo) + __uint_as_float(hi);
}

// ---------------- mbarrier / cluster helpers -----------------------------------
__device__ __forceinline__ uint32_t ctarank() {
    uint32_t r;
    asm("mov.u32 %0, %%cluster_ctarank;" : "=r"(r));
    return r;
}
__device__ __forceinline__ void mbar_init(uint32_t a, uint32_t cnt) {
    asm volatile("mbarrier.init.shared.b64 [%0], %1;" :: "r"(a), "r"(cnt) : "memory");
}
__device__ __forceinline__ void mbar_expect(uint32_t a, uint32_t bytes) {
    asm volatile("mbarrier.arrive.expect_tx.shared.b64 _, [%0], %1;"
                 :: "r"(a), "r"(bytes) : "memory");
}
__device__ __forceinline__ void mbar_arrive_rank0(uint32_t a) {
    asm volatile(
        "{\n\t.reg .b32 ra;\n\t"
        "mapa.shared::cluster.u32 ra, %0, 0;\n\t"
        "mbarrier.arrive.shared::cluster.b64 _, [ra];\n\t}"
        :: "r"(a) : "memory");
}
__device__ __forceinline__ void mbar_wait_acq(uint32_t a, uint32_t ph) {
    asm volatile(
        "{\n\t.reg .pred P;\n\t"
        "WL_%=:\n\t"
        "mbarrier.try_wait.parity.acquire.cta.shared::cta.b64 P, [%0], %1, 0x989680;\n\t"
        "@P bra.uni WD_%=;\n\t"
        "bra.uni WL_%=;\n\t"
        "WD_%=:\n\t}"
        :: "r"(a), "r"(ph) : "memory");
}
__device__ __forceinline__ void mbar_wait_rlx(uint32_t a, uint32_t ph) {
    asm volatile(
        "{\n\t.reg .pred P;\n\t"
        "WL_%=:\n\t"
        "mbarrier.try_wait.parity.relaxed.cta.shared::cta.b64 P, [%0], %1, 0x989680;\n\t"
        "@P bra.uni WD_%=;\n\t"
        "bra.uni WL_%=;\n\t"
        "WD_%=:\n\t}"
        :: "r"(a), "r"(ph) : "memory");
}
#define CONS_BAR() asm volatile("bar.sync 1, 512;" ::: "memory")
#define CLUSTER_ARV() asm volatile("barrier.cluster.arrive.aligned;" ::: "memory")
#define CLUSTER_WT()  asm volatile("barrier.cluster.wait.aligned;" ::: "memory")

// ---------------- one k2 (2 k's) of LSTM math -----------------------------------
__device__ __forceinline__ void k2_block(uint4 wA, uint4 wB,
                                         ulonglong2 xv0, ulonglong2 xv1,
                                         ulonglong2 xv2, ulonglong2 xv3,
                                         unsigned long long* acc) {
    unsigned long long wi = cvtw(wA.x), wf = cvtw(wA.y), wg = cvtw(wA.z), wo = cvtw(wA.w);
    fma2(acc[0], wi, xv0.x); fma2(acc[4], wf, xv0.x); fma2(acc[8],  wg, xv0.x); fma2(acc[12], wo, xv0.x);
    fma2(acc[1], wi, xv1.x); fma2(acc[5], wf, xv1.x); fma2(acc[9],  wg, xv1.x); fma2(acc[13], wo, xv1.x);
    fma2(acc[2], wi, xv2.x); fma2(acc[6], wf, xv2.x); fma2(acc[10], wg, xv2.x); fma2(acc[14], wo, xv2.x);
    fma2(acc[3], wi, xv3.x); fma2(acc[7], wf, xv3.x); fma2(acc[11], wg, xv3.x); fma2(acc[15], wo, xv3.x);
    wi = cvtw(wB.x); wf = cvtw(wB.y); wg = cvtw(wB.z); wo = cvtw(wB.w);
    fma2(acc[0], wi, xv0.y); fma2(acc[4], wf, xv0.y); fma2(acc[8],  wg, xv0.y); fma2(acc[12], wo, xv0.y);
    fma2(acc[1], wi, xv1.y); fma2(acc[5], wf, xv1.y); fma2(acc[9],  wg, xv1.y); fma2(acc[13], wo, xv1.y);
    fma2(acc[2], wi, xv2.y); fma2(acc[6], wf, xv2.y); fma2(acc[10], wg, xv2.y); fma2(acc[14], wo, xv2.y);
    fma2(acc[3], wi, xv3.y); fma2(acc[7], wf, xv3.y); fma2(acc[11], wg, xv3.y); fma2(acc[15], wo, xv3.y);
}

// ---------------- main persistent kernel ---------------------------------------
// 128 CTAs in 16 clusters of 8. CTA owns 4 batch rows. Rank 0 of each cluster
// multicasts the 2.2MB/step weight image through a 3x64KB smem ring to all 8.
// Ring pacing is per-WARP (no CTA barriers in the chunk loops):
//   warp: wait full[s] -> read -> (data-fence) -> lane0 remote-arrive rank0 empty[s]
//   warp0-lane0 additionally re-arms local full[s] (arrive.expect_tx) BEFORE its
//   empty arrive, so the producer (gated on empty, count=8x16=128) can never
//   write an un-armed slot.
__global__ void __launch_bounds__(TPB, 1) __cluster_dims__(CLU, 1, 1)
gen_kernel(const float* __restrict__ z,         // [B][S][ZS]
           const float* __restrict__ prev_gen,  // [B][FLATD]
           const float* __restrict__ fc1_b,     // [HID]
           const float* __restrict__ fc2_w,     // [FLATD][HID]
           const float* __restrict__ fc2_b,     // [FLATD]
           float* __restrict__ out)             // [B][S][FLATD]
{
    extern __shared__ __align__(16) char sm[];
    char* ring = sm + RING_OFF;
    const uint32_t ring_sa = (uint32_t)__cvta_generic_to_shared(ring);
    const uint32_t mb = (uint32_t)__cvta_generic_to_shared(sm + MB_OFF);
    float2 (*A1)[HID] = (float2(*)[HID])(sm + A1_OFF);   // (x_t, h1_{t-1})
    float2 (*A2)[HID] = (float2(*)[HID])(sm + A2_OFF);   // (h1_t, h2_{t-1})
    float (*red)[HID] = (float(*)[HID])(sm + RED_OFF);   // cross-half partials
    float (*insm)[128] = (float(*)[128])(sm + INSM_OFF); // [row][k]; 100..104=prev, >=105 zero

    const int tid = threadIdx.x;
    const uint32_t rank = ctarank();
    const int b0 = blockIdx.x * 4;

    // ---- init ----
    if (tid == 0) {
#pragma unroll
        for (int s = 0; s < NSLOT; s++) {
            mbar_init(mb + 16 * s, 1);                 // full[s]
            mbar_init(mb + 16 * s + 8, CLU * NWARPC);  // empty[s] (rank0's is used)
        }
#pragma unroll
        for (int s = 0; s < NSLOT; s++) mbar_expect(mb + 16 * s, CHUNK_B);  // arm use 0
    }
    if (tid < 512) {
        const int u = tid & (HID - 1);
        if (tid < 256) {
#pragma unroll
            for (int r = 0; r < 4; r++) {
                A1[r][u].y = 0.0f;
                A2[r][u].y = 0.0f;
            }
        }
        if (tid < 20) {
            int r = tid / 5, j = tid % 5;
            insm[r][ZS + j] = prev_gen[(b0 + r) * FLATD + j];
        }
        if (tid < 92) {  // zero pad cols 105..127
            int r = tid / 23, k = IN1 + tid % 23;
            insm[r][k] = 0.0f;
        }
    }
    __syncthreads();   // all 544: init visible
    CLUSTER_ARV();
    CLUSTER_WT();      // all CTAs armed before any multicast

    if (tid < 512) {
        // ================= CONSUMER =================
        const int u = tid & (HID - 1);
        const int half = tid >> 8;
        const int lane = tid & 31;
        const bool is_w0 = (tid < 32);   // warp 0 re-arms full[]
        float c1[2] = {0.f, 0.f};
        float c2[2] = {0.f, 0.f};
        const float fb = fc1_b[u];
        const float4 b1v = ((const float4*)g_b1)[u];
        const float4 b2v = ((const float4*)g_b2)[u];
        int cg = 0;  // global chunk counter (uniform across consumer threads)

        for (int t = 0; t < SEQL; ++t) {
            // ---- stage 1: z rows into insm ----
            if (tid < 4 * ZS) {
                int r = tid / ZS, k = tid % ZS;
                insm[r][k] = z[(size_t)(b0 + r) * (SEQL * ZS) + (size_t)t * ZS + k];
            }
            CONS_BAR();  // B1: insm ready

            // ---- stage 2: fc1 (2 chunks) -> A1.x; half0 rows 0,1 / half1 rows 2,3 ----
            {
                int r0 = half * 2, r1 = r0 + 1;
                float a0 = fb, a1 = fb;
#pragma unroll 1
                for (int j = 0; j < 2; j++) {
                    int s = cg % NSLOT;
                    mbar_wait_acq(mb + 16 * s, (cg / NSLOT) & 1);
                    const float* wf = (const float*)(ring + s * CHUNK_B);
#pragma unroll 8
                    for (int k = 0; k < 64; k++) {
                        float w = wf[k * HID + u];
                        a0 += w * insm[r0][64 * j + k];
                        a1 += w * insm[r1][64 * j + k];
                    }
                    asm volatile("" : "+f"(a0));  // all 64 LDS consumed before signal
                    if (lane == 0) {
                        if (is_w0) mbar_expect(mb + 16 * s, CHUNK_B);  // re-arm next use
                        mbar_arrive_rank0(mb + 16 * s + 8);            // slot consumed
                    }
                    cg++;
                }
                A1[r0][u].x = fmaxf(a0, 0.0f);
                A1[r1][u].x = fmaxf(a1, 0.0f);
            }
            CONS_BAR();  // B2: A1 = (x, h1prev) ready

            // ---- stages 3&4: LSTM1 then LSTM2, 16 chunks each ----
#pragma unroll 1
            for (int stage = 0; stage < 2; stage++) {
                unsigned long long acc[16];
#pragma unroll
                for (int j = 0; j < 16; j++) acc[j] = 0ull;
                const float2(*Ax)[HID] = stage ? A2 : A1;
                const ulonglong2* x0 = (const ulonglong2*)Ax[0];
                const ulonglong2* x1 = (const ulonglong2*)Ax[1];
                const ulonglong2* x2 = (const ulonglong2*)Ax[2];
                const ulonglong2* x3 = (const ulonglong2*)Ax[3];
#pragma unroll 1
                for (int jc = 0; jc < 16; jc++) {
                    int s = cg % NSLOT;
                    mbar_wait_acq(mb + 16 * s, (cg / NSLOT) & 1);
                    const uint4* wp = (const uint4*)(ring + s * CHUNK_B) + (8 * half) * HID + u;
                    int xb = 8 * jc + 4 * half;
#pragma unroll
                    for (int kk = 0; kk < 4; kk++) {
                        uint4 wA = wp[(2 * kk) * HID];
                        uint4 wB = wp[(2 * kk + 1) * HID];
                        k2_block(wA, wB, x0[xb + kk], x1[xb + kk], x2[xb + kk], x3[xb + kk], acc);
                    }
                    // acc[0]'s FFMA chain consumes every loaded uint4 -> LDS done
                    asm volatile("" : "+l"(acc[0]));
                    if (lane == 0) {
                        if (is_w0) mbar_expect(mb + 16 * s, CHUNK_B);
                        mbar_arrive_rank0(mb + 16 * s + 8);
                    }
                    cg++;
                }
                // merge halves + activations (other half's rows via red)
                int ro = 2 * (1 - half);
#pragma unroll
                for (int g = 0; g < 4; g++) {
                    red[g * 4 + ro][u] = redu0(acc[g * 4 + ro]);
                    red[g * 4 + ro + 1][u] = redu0(acc[g * 4 + ro + 1]);
                }
                CONS_BAR();  // B3/B5: partials ready; all Ax reads done
                const float4 bv = stage ? b2v : b1v;
                float* cc = stage ? c2 : c1;
                int rs = 2 * half;
#pragma unroll
                for (int rr = 0; rr < 2; rr++) {
                    int r = rs + rr;
                    float iv = sigm_f(redu0(acc[0 + r]) + red[0 + r][u] + bv.x);
                    float fv = sigm_f(redu0(acc[4 + r]) + red[4 + r][u] + bv.y);
                    float gv = tanh_f(redu0(acc[8 + r]) + red[8 + r][u] + bv.z);
                    float ov = sigm_f(redu0(acc[12 + r]) + red[12 + r][u] + bv.w);
                    float cn = fv * cc[rr] + iv * gv;
                    cc[rr] = cn;
                    float hv = ov * tanh_f(cn);
                    if (stage == 0) {
                        A1[r][u].y = hv;  // h1 for t+1
                        A2[r][u].x = hv;  // input to LSTM2 now
                    } else {
                        A2[r][u].y = hv;  // h2 for t+1 / fc2
                    }
                }
                CONS_BAR();  // B4/B6
            }

            // ---- stage 5: fc2 + tanh -> prev + output ----
            {
                int wid = tid >> 5;
                for (int p = wid; p < 20; p += 16) {
                    int j = p >> 2, r = p & 3;
                    float s = 0.0f;
#pragma unroll
                    for (int i = 0; i < 8; i++) {
                        int uu = lane + 32 * i;
                        s += fc2_w[j * HID + uu] * A2[r][uu].y;
                    }
#pragma unroll
                    for (int o = 16; o; o >>= 1) s += __shfl_down_sync(0xffffffffu, s, o);
                    if (lane == 0) {
                        float v = tanh_f(s + fc2_b[j]);
                        insm[r][ZS + j] = v;
                        out[(size_t)(b0 + r) * (SEQL * FLATD) + (size_t)t * FLATD + j] = v;
                    }
                }
            }
            // next iteration's B1 orders stage5 insm writes before fc1 reads
        }
    } else if (tid == 512 && rank == 0) {
        // ================= PRODUCER (one lane) =================
        int s = 0, use = 0;
        for (int c = 0; c < SEQL * NCHUNK; ++c) {
            if (c >= NSLOT) mbar_wait_rlx(mb + 16 * s + 8, (use + 1) & 1);  // == (use-1)&1
            const char* src = (const char*)g_stream + (size_t)(c % NCHUNK) * CHUNK_B;
            asm volatile(
                "cp.async.bulk.shared::cluster.global.mbarrier::complete_tx::bytes"
                ".multicast::cluster [%0], [%1], %2, [%3], %4;"
                :: "r"(ring_sa + s * CHUNK_B), "l"(src), "r"(CHUNK_B),
                   "r"(mb + 16 * s), "h"((unsigned short)0xFF)
                : "memory");
            if (++s == NSLOT) { s = 0; use++; }
        }
    }

    CLUSTER_ARV();
    CLUSTER_WT();  // no CTA exits while multicasts may target it
}

// ---------------- launch --------------------------------------------------------
extern "C" void kernel_launch(void* const* d_in, const int* in_sizes, int n_in,
                              void* d_out, int out_size) {
    (void)in_sizes; (void)n_in; (void)out_size;
    const float* z        = (const float*)d_in[0];
    const float* prev_gen = (const float*)d_in[1];
    const float* fc1_w    = (const float*)d_in[2];
    const float* fc1_b    = (const float*)d_in[3];
    const float* w_ih1    = (const float*)d_in[4];
    const float* w_hh1    = (const float*)d_in[5];
    const float* b_ih1    = (const float*)d_in[6];
    const float* b_hh1    = (const float*)d_in[7];
    const float* w_ih2    = (const float*)d_in[8];
    const float* w_hh2    = (const float*)d_in[9];
    const float* b_ih2    = (const float*)d_in[10];
    const float* b_hh2    = (const float*)d_in[11];
    const float* fc2_w    = (const float*)d_in[12];
    const float* fc2_b    = (const float*)d_in[13];
    float* out = (float*)d_out;

    const int total = NCHUNK * CHUNK_U + 2 * HID * 4;
    repack_kernel<<<(total + 255) / 256, 256>>>(w_ih1, w_hh1, w_ih2, w_hh2,
                                                b_ih1, b_hh1, b_ih2, b_hh2, fc1_w);

    cudaFuncSetAttribute(gen_kernel, cudaFuncAttributeMaxDynamicSharedMemorySize,
                         SMEM_TOT);
    gen_kernel<<<BATCH / 4, TPB, SMEM_TOT>>>(z, prev_gen, fc1_b, fc2_w, fc2_b, out);
}